// round 1
// baseline (speedup 1.0000x reference)
#include <cuda_runtime.h>
#include <cstdint>

// Problem constants
#define BB    256   // batches
#define NROWS 1024  // rows per batch (M)
#define INK   256   // K
#define OUTN  256   // N (output features)

// Tiling
#define BM 128
#define BN 128
#define BK 32
#define AS_STRIDE 36    // (4*row + t) % 32 unique over row0..7, t0..3 -> conflict-free A frag loads
#define BS_STRIDE 136   // (8*t + g) % 32 unique over t0..3, g0..7 -> conflict-free B frag loads

#define SMEM_STAGE_A (BM * AS_STRIDE)          // floats
#define SMEM_STAGE_B (BK * BS_STRIDE)          // floats
#define SMEM_FLOATS  (2 * (SMEM_STAGE_A + SMEM_STAGE_B))
#define SMEM_BYTES   (SMEM_FLOATS * 4)         // 71680 bytes

__device__ __forceinline__ float to_tf32(float f) {
    unsigned u;
    asm("cvt.rna.tf32.f32 %0, %1;" : "=r"(u) : "f"(f));
    return __uint_as_float(u);
}

// Robust index fetch: buffer may be int64 (reference dtype) or int32 (JAX default
// without x64). Values are in [0,1024), so if int64, every odd 32-bit word of the
// first 8 values is 0. If int32, the odd words are random indices (all-zero prob
// ~(2^-10)^8, negligible, and deterministic per fixed seed).
__device__ __forceinline__ int fetch_index(const void* p, int b) {
    const int* q = (const int*)p;
    int odd_or = q[1] | q[3] | q[5] | q[7] | q[9] | q[11] | q[13] | q[15];
    return (odd_or == 0) ? q[2 * b] : q[b];
}

__global__ void __launch_bounds__(256, 1)
alw_tf32_kernel(const float* __restrict__ x,
                const void*  __restrict__ indices,
                const float* __restrict__ w,
                const float* __restrict__ bias,
                float* __restrict__ out) {
    extern __shared__ float smem[];
    float* As = smem;                       // [2][BM][AS_STRIDE]
    float* Bs = smem + 2 * SMEM_STAGE_A;    // [2][BK][BS_STRIDE]

    const int tid  = threadIdx.x;
    const int lane = tid & 31;
    const int warp = tid >> 5;
    const int g = lane >> 2;     // group id (0..7)
    const int t = lane & 3;      // thread-in-group (0..3)

    const int wm32 = (warp >> 1) * 32;   // warp M offset within block tile (4 warps in M)
    const int wn64 = (warp & 1) * 64;    // warp N offset within block tile (2 warps in N)

    const int b  = blockIdx.z;
    const int m0 = blockIdx.y * BM;
    const int n0 = blockIdx.x * BN;
    const int ch = fetch_index(indices, b);

    const float* __restrict__ xb = x + ((size_t)b * NROWS + m0) * INK;
    const float* __restrict__ wb = w + ((size_t)ch * INK) * OUTN + n0;

    // Per-thread global load coordinates (4 float4 each for A and B per stage)
    // A: 128 rows x 32 cols = 1024 float4; row = idx>>3, c4 = idx&7
    // B:  32 rows x 128 cols = 1024 float4; kr  = idx>>5, c4 = idx&31
    int a_row[4], a_c4[4], b_kr[4], b_c4[4];
#pragma unroll
    for (int i = 0; i < 4; ++i) {
        int idx = tid + i * 256;
        a_row[i] = idx >> 3;  a_c4[i] = idx & 7;
        b_kr[i]  = idx >> 5;  b_c4[i] = idx & 31;
    }

    float4 pa[4], pb[4];

    // ---- load tile kt=0 into registers ----
#pragma unroll
    for (int i = 0; i < 4; ++i) {
        pa[i] = *(const float4*)(xb + (size_t)a_row[i] * INK + a_c4[i] * 4);
        pb[i] = *(const float4*)(wb + (size_t)b_kr[i] * OUTN + b_c4[i] * 4);
    }

    // store stage 0 (with tf32 rounding)
#pragma unroll
    for (int i = 0; i < 4; ++i) {
        float* ap = As + a_row[i] * AS_STRIDE + a_c4[i] * 4;
        ap[0] = to_tf32(pa[i].x); ap[1] = to_tf32(pa[i].y);
        ap[2] = to_tf32(pa[i].z); ap[3] = to_tf32(pa[i].w);
        float* bp = Bs + b_kr[i] * BS_STRIDE + b_c4[i] * 4;
        bp[0] = to_tf32(pb[i].x); bp[1] = to_tf32(pb[i].y);
        bp[2] = to_tf32(pb[i].z); bp[3] = to_tf32(pb[i].w);
    }
    __syncthreads();

    float c[2][8][4];
#pragma unroll
    for (int mi = 0; mi < 2; ++mi)
#pragma unroll
        for (int ni = 0; ni < 8; ++ni)
#pragma unroll
            for (int r = 0; r < 4; ++r) c[mi][ni][r] = 0.0f;

    const int NSTAGE = INK / BK;  // 8
#pragma unroll 1
    for (int kt = 0; kt < NSTAGE; ++kt) {
        const int buf = kt & 1;
        const float* Asb = As + buf * SMEM_STAGE_A;
        const float* Bsb = Bs + buf * SMEM_STAGE_B;

        // prefetch next tile into registers
        if (kt + 1 < NSTAGE) {
            const int k0 = (kt + 1) * BK;
#pragma unroll
            for (int i = 0; i < 4; ++i) {
                pa[i] = *(const float4*)(xb + (size_t)a_row[i] * INK + k0 + a_c4[i] * 4);
                pb[i] = *(const float4*)(wb + (size_t)(k0 + b_kr[i]) * OUTN + b_c4[i] * 4);
            }
        }

        // compute 4 k-steps of 8 from this stage
#pragma unroll
        for (int kk = 0; kk < BK; kk += 8) {
            unsigned af[2][4];
#pragma unroll
            for (int mi = 0; mi < 2; ++mi) {
                const float* p = Asb + (wm32 + mi * 16 + g) * AS_STRIDE + kk + t;
                af[mi][0] = __float_as_uint(p[0]);
                af[mi][1] = __float_as_uint(p[8 * AS_STRIDE]);
                af[mi][2] = __float_as_uint(p[4]);
                af[mi][3] = __float_as_uint(p[8 * AS_STRIDE + 4]);
            }
            unsigned bf[8][2];
#pragma unroll
            for (int ni = 0; ni < 8; ++ni) {
                const float* q = Bsb + (kk + t) * BS_STRIDE + wn64 + ni * 8 + g;
                bf[ni][0] = __float_as_uint(q[0]);
                bf[ni][1] = __float_as_uint(q[4 * BS_STRIDE]);
            }
#pragma unroll
            for (int mi = 0; mi < 2; ++mi)
#pragma unroll
                for (int ni = 0; ni < 8; ++ni) {
                    asm volatile(
                        "mma.sync.aligned.m16n8k8.row.col.f32.tf32.tf32.f32 "
                        "{%0,%1,%2,%3}, {%4,%5,%6,%7}, {%8,%9}, {%0,%1,%2,%3};"
                        : "+f"(c[mi][ni][0]), "+f"(c[mi][ni][1]),
                          "+f"(c[mi][ni][2]), "+f"(c[mi][ni][3])
                        : "r"(af[mi][0]), "r"(af[mi][1]), "r"(af[mi][2]), "r"(af[mi][3]),
                          "r"(bf[ni][0]), "r"(bf[ni][1]));
                }
        }

        // store prefetched tile into the other stage
        if (kt + 1 < NSTAGE) {
            float* An = As + (buf ^ 1) * SMEM_STAGE_A;
            float* Bn = Bs + (buf ^ 1) * SMEM_STAGE_B;
#pragma unroll
            for (int i = 0; i < 4; ++i) {
                float* ap = An + a_row[i] * AS_STRIDE + a_c4[i] * 4;
                ap[0] = to_tf32(pa[i].x); ap[1] = to_tf32(pa[i].y);
                ap[2] = to_tf32(pa[i].z); ap[3] = to_tf32(pa[i].w);
                float* bp = Bn + b_kr[i] * BS_STRIDE + b_c4[i] * 4;
                bp[0] = to_tf32(pb[i].x); bp[1] = to_tf32(pb[i].y);
                bp[2] = to_tf32(pb[i].z); bp[3] = to_tf32(pb[i].w);
            }
            __syncthreads();
        }
    }

    // ---- epilogue: add bias, write out ----
    const float* __restrict__ biasp = bias + (size_t)ch * OUTN + n0;
    float* __restrict__ outb = out + ((size_t)b * NROWS + m0) * OUTN + n0;

#pragma unroll
    for (int ni = 0; ni < 8; ++ni) {
        const int cbase = wn64 + ni * 8 + 2 * t;
        const float bv0 = biasp[cbase];
        const float bv1 = biasp[cbase + 1];
#pragma unroll
        for (int mi = 0; mi < 2; ++mi) {
            const int r0 = wm32 + mi * 16 + g;
            float2 v0 = make_float2(c[mi][ni][0] + bv0, c[mi][ni][1] + bv1);
            *(float2*)(outb + (size_t)r0 * OUTN + cbase) = v0;
            float2 v1 = make_float2(c[mi][ni][2] + bv0, c[mi][ni][3] + bv1);
            *(float2*)(outb + (size_t)(r0 + 8) * OUTN + cbase) = v1;
        }
    }
}

extern "C" void kernel_launch(void* const* d_in, const int* in_sizes, int n_in,
                              void* d_out, int out_size) {
    const float* x      = (const float*)d_in[0];
    const void*  indices = d_in[1];
    const float* w      = (const float*)d_in[2];
    const float* bias   = (const float*)d_in[3];
    float* out = (float*)d_out;

    cudaFuncSetAttribute(alw_tf32_kernel,
                         cudaFuncAttributeMaxDynamicSharedMemorySize, SMEM_BYTES);

    dim3 grid(OUTN / BN, NROWS / BM, BB);   // (2, 8, 256)
    alw_tf32_kernel<<<grid, 256, SMEM_BYTES>>>(x, indices, w, bias, out);
}

// round 6
// speedup vs baseline: 1.2425x; 1.2425x over previous
#include <cuda_runtime.h>
#include <cstdint>

#define BB    256
#define NROWS 1024
#define INK   256
#define OUTN  256

// SMEM layout (bytes) for tcgen05 path
#define SMEM_TMEM_PTR 0
#define SMEM_MBAR0    8
#define SMEM_MBAR1    16
#define SMEM_BIAS     64            // 256 floats = 1KB
#define SMEM_A        2048          // 2 stages x 16KB (128 rows x 128B, SW128)
#define A_STAGE       16384
#define SMEM_B        34816         // 2 stages x 32KB (256 rows x 128B, SW128)
#define B_STAGE       32768
#define SMEM_TOTAL    100352

#define TMEM_COLS 256

// Arch gate: tcgen05 only exists in the arch-specific (sm_103a) compilation.
// The harness also builds a plain compute_103/sm_103 pass which must compile —
// it gets a correct smem-tiled FFMA fallback (never expected to be loaded on
// the sm_103a device, but correct if it ever is).
#if defined(__CUDA_ARCH__) && (defined(__CUDA_ARCH_FEAT_SM103_ALL) || \
    (defined(__CUDA_ARCH_SPECIFIC__)))
#define ALW_TCGEN05 1
#else
#define ALW_TCGEN05 0
#endif

// int64-vs-int32 index buffer detection (values < 1024 -> int64 high words all 0)
static __device__ __forceinline__ int fetch_index(const void* p, int b) {
    const int* q = (const int*)p;
    int odd_or = q[1] | q[3] | q[5] | q[7] | q[9] | q[11] | q[13] | q[15];
    return (odd_or == 0) ? q[2 * b] : q[b];
}

#if ALW_TCGEN05

// tcgen05 instruction descriptor, kind::tf32:
// c_format F32=1 @[4:5], a_format TF32=2 @[7:9], b_format TF32=2 @[10:12],
// N>>3 @[17:22], M>>4 @[24:28]; K-major both
#define IDESC ((1u << 4) | (2u << 7) | (2u << 10) | ((OUTN / 8) << 17) | ((128 / 16) << 24))

#define SWZ(o) ((uint32_t)(o) ^ ((((uint32_t)(o)) >> 3) & 0x70))

// SW128 K-major smem descriptor base: layout=2, version=1, SBO=64, LBO=1
static __device__ __forceinline__ uint64_t make_desc(uint32_t addr) {
    const uint64_t base = (uint64_t(2) << 61) | (uint64_t(1) << 46) |
                          (uint64_t(64) << 32) | (uint64_t(1) << 16);
    return base | ((uint64_t)(addr >> 4) & 0x3FFF);
}

static __device__ __forceinline__ uint32_t smem_u32(const void* p) {
    uint32_t a;
    asm("{ .reg .u64 t; cvta.to.shared.u64 t, %1; cvt.u32.u64 %0, t; }" : "=r"(a) : "l"(p));
    return a;
}

static __device__ __forceinline__ uint32_t elect_one() {
    uint32_t p;
    asm volatile("{\n\t.reg .pred p;\n\telect.sync _|p, 0xFFFFFFFF;\n\tselp.b32 %0,1,0,p;\n\t}" : "=r"(p));
    return p;
}

static __device__ __forceinline__ float tf32r(float f) {
    uint32_t u;
    asm("cvt.rna.tf32.f32 %0, %1;" : "=r"(u) : "f"(f));
    return __uint_as_float(u);
}

#define MBARRIER_INIT(addr, cnt) \
    asm volatile("mbarrier.init.shared.b64 [%0], %1;" :: "r"((uint32_t)(addr)), "r"((uint32_t)(cnt)) : "memory")

#define MBARRIER_WAIT_PARITY(mbar_addr, phase_parity) do {                                  \
    uint32_t _mbar = (uint32_t)(mbar_addr);                                                 \
    uint32_t _par  = (uint32_t)(phase_parity);                                              \
    uint32_t _done;                                                                         \
    asm volatile("{\n\t.reg .pred p;\n\t"                                                   \
                 "mbarrier.try_wait.parity.acquire.cta.shared::cta.b64 p, [%1], %2;\n\t"    \
                 "selp.b32 %0, 1, 0, p;\n\t}"                                               \
                 : "=r"(_done) : "r"(_mbar), "r"(_par) : "memory");                         \
    if (!_done) {                                                                           \
        asm volatile("{\n\t.reg .pred P1;\n\t"                                              \
            "WAIT_LOOP_%=:\n\t"                                                             \
            "mbarrier.try_wait.parity.acquire.cta.shared::cta.b64 P1, [%0], %1, 0x989680;\n\t" \
            "@P1 bra.uni WAIT_DONE_%=;\n\t"                                                 \
            "bra.uni WAIT_LOOP_%=;\n\t"                                                     \
            "WAIT_DONE_%=:\n\t}"                                                            \
            :: "r"(_mbar), "r"(_par) : "memory");                                           \
    }                                                                                       \
} while (0)

#define TCGEN05_ALLOC(smem_addr, ncols) \
    asm volatile("tcgen05.alloc.cta_group::1.sync.aligned.shared::cta.b32 [%0], %1;" \
                 :: "r"((uint32_t)(smem_addr)), "r"((uint32_t)(ncols)) : "memory")
#define TCGEN05_DEALLOC(tmem, ncols) \
    asm volatile("tcgen05.dealloc.cta_group::1.sync.aligned.b32 %0, %1;" \
                 :: "r"(tmem), "r"((uint32_t)(ncols)))
#define TCGEN05_RELINQ() \
    asm volatile("tcgen05.relinquish_alloc_permit.cta_group::1.sync.aligned;")
#define TCGEN05_COMMIT(mbar) \
    asm volatile("tcgen05.commit.cta_group::1.mbarrier::arrive::one.shared::cluster.b64 [%0];" \
                 :: "r"((uint32_t)(mbar)) : "memory")
#define TCGEN05_FENCE_AFTER() \
    asm volatile("tcgen05.fence::after_thread_sync;" ::: "memory")
#define TCGEN05_FENCE_BEFORE() \
    asm volatile("tcgen05.fence::before_thread_sync;" ::: "memory")
#define TCGEN05_WAIT_LD() \
    asm volatile("tcgen05.wait::ld.sync.aligned;" ::: "memory")

#define TCGEN05_LD_32X32B_X32(r, tmem_addr) \
    asm volatile( \
        "tcgen05.ld.sync.aligned.32x32b.x32.b32 " \
        "{%0, %1, %2, %3, %4, %5, %6, %7, " \
        " %8, %9, %10, %11, %12, %13, %14, %15, " \
        " %16, %17, %18, %19, %20, %21, %22, %23, " \
        " %24, %25, %26, %27, %28, %29, %30, %31}, [%32];" \
        : "=r"((r)[0]),  "=r"((r)[1]),  "=r"((r)[2]),  "=r"((r)[3]), \
          "=r"((r)[4]),  "=r"((r)[5]),  "=r"((r)[6]),  "=r"((r)[7]), \
          "=r"((r)[8]),  "=r"((r)[9]),  "=r"((r)[10]), "=r"((r)[11]), \
          "=r"((r)[12]), "=r"((r)[13]), "=r"((r)[14]), "=r"((r)[15]), \
          "=r"((r)[16]), "=r"((r)[17]), "=r"((r)[18]), "=r"((r)[19]), \
          "=r"((r)[20]), "=r"((r)[21]), "=r"((r)[22]), "=r"((r)[23]), \
          "=r"((r)[24]), "=r"((r)[25]), "=r"((r)[26]), "=r"((r)[27]), \
          "=r"((r)[28]), "=r"((r)[29]), "=r"((r)[30]), "=r"((r)[31]) \
        : "r"(tmem_addr))

static __device__ __forceinline__ void mma_tf32_ss(uint32_t d_tmem, uint64_t a_desc,
                                                   uint64_t b_desc, uint32_t idesc,
                                                   uint32_t enable) {
    asm volatile(
        "{\n\t"
        ".reg .pred p;\n\t"
        "setp.ne.u32 p, %4, 0;\n\t"
        "tcgen05.mma.cta_group::1.kind::tf32 [%0], %1, %2, %3, {%5, %5, %5, %5}, p;\n\t"
        "}"
        :: "r"(d_tmem), "l"(a_desc), "l"(b_desc), "r"(idesc), "r"(enable), "r"(0u)
        : "memory");
}

#endif // ALW_TCGEN05

__global__ void __launch_bounds__(256, 2)
alw_kernel(const float* __restrict__ x,
           const void*  __restrict__ indices,
           const float* __restrict__ w,
           const float* __restrict__ bias,
           float* __restrict__ out) {
#if ALW_TCGEN05
    extern __shared__ char smem[];
    const uint32_t sb = smem_u32(smem);
    const int tid  = threadIdx.x;
    const int lane = tid & 31;
    const int wid  = tid >> 5;

    const int mtile = blockIdx.x;
    const int b     = blockIdx.y;
    const int ch    = fetch_index(indices, b);

    const float* __restrict__ xb = x + ((size_t)b * NROWS + mtile * 128) * INK;
    const float* __restrict__ wb = w + (size_t)ch * (INK * OUTN);

    if (wid == 0) {
        TCGEN05_ALLOC(sb + SMEM_TMEM_PTR, TMEM_COLS);
        TCGEN05_RELINQ();
    }
    if (tid == 0) {
        MBARRIER_INIT(sb + SMEM_MBAR0, 1);
        MBARRIER_INIT(sb + SMEM_MBAR1, 1);
    }
    ((float*)(smem + SMEM_BIAS))[tid] = bias[(size_t)ch * OUTN + tid];
    __syncthreads();

    uint32_t tmem;
    asm volatile("ld.shared.b32 %0, [%1];" : "=r"(tmem) : "r"(sb + SMEM_TMEM_PTR));

    const int kof  = lane >> 3;   // 0..3 : k offset inside warp (B transpose STS)
    const int c4of = lane & 7;    // 0..7 : float4-column offset inside warp

#pragma unroll
    for (int kt = 0; kt < 8; ++kt) {
        const int buf = kt & 1;
        const uint32_t mbar = sb + (buf ? SMEM_MBAR1 : SMEM_MBAR0);

        if (kt >= 2) {
            MBARRIER_WAIT_PARITY(mbar, ((kt - 2) >> 1) & 1);
        }

        // ---- A: 128 rows x 32 floats, K-major, SW128, tf32-rounded ----
        {
            const float* asrc = xb + kt * 32;
            char* Ab = smem + SMEM_A + buf * A_STAGE;
#pragma unroll
            for (int i = 0; i < 4; ++i) {
                int idx = i * 256 + tid;
                int row = idx >> 3, c4 = idx & 7;
                float4 v = *(const float4*)(asrc + (size_t)row * INK + c4 * 4);
                float4 t = make_float4(tf32r(v.x), tf32r(v.y), tf32r(v.z), tf32r(v.w));
                *(float4*)(Ab + SWZ(row * 128 + c4 * 16)) = t;
            }
        }

        // ---- B: transpose w[k][n] -> Bs[n][k], 256 rows x 32 floats, SW128 ----
        {
            const float* bsrc = wb + (size_t)(kt * 32) * OUTN;
            char* Bb = smem + SMEM_B + buf * B_STAGE;
#pragma unroll
            for (int i = 0; i < 8; ++i) {
                int u  = i * 8 + wid;               // 0..63
                int k  = ((u >> 3) << 2) + kof;     // 0..31
                int c4 = ((u & 7) << 3) + c4of;     // 0..63
                float4 v = *(const float4*)(bsrc + (size_t)k * OUTN + c4 * 4);
                int nb = c4 * 4;
                *(float*)(Bb + SWZ((nb + 0) * 128 + k * 4)) = tf32r(v.x);
                *(float*)(Bb + SWZ((nb + 1) * 128 + k * 4)) = tf32r(v.y);
                *(float*)(Bb + SWZ((nb + 2) * 128 + k * 4)) = tf32r(v.z);
                *(float*)(Bb + SWZ((nb + 3) * 128 + k * 4)) = tf32r(v.w);
            }
        }

        __syncthreads();

        if (wid == 0) {
            if (elect_one()) {
                asm volatile("fence.proxy.async.shared::cta;" ::: "memory");
                uint64_t ad = make_desc(sb + SMEM_A + buf * A_STAGE);
                uint64_t bd = make_desc(sb + SMEM_B + buf * B_STAGE);
#pragma unroll
                for (int kk = 0; kk < 4; ++kk) {
                    mma_tf32_ss(tmem, ad + kk * 2, bd + kk * 2, IDESC,
                                (uint32_t)((kt | kk) != 0));
                }
                TCGEN05_COMMIT(mbar);
            }
        }
    }

    MBARRIER_WAIT_PARITY(sb + SMEM_MBAR0, 1);
    MBARRIER_WAIT_PARITY(sb + SMEM_MBAR1, 1);
    TCGEN05_FENCE_AFTER();

    const int sub  = wid & 3;
    const int half = wid >> 2;
    const uint32_t woff = (uint32_t)sub << 21;
    const int m = mtile * 128 + sub * 32 + lane;
    float* __restrict__ orow = out + ((size_t)b * NROWS + m) * OUTN;
    const float* sbias = (const float*)(smem + SMEM_BIAS);

#pragma unroll
    for (int g = 0; g < 4; ++g) {
        const int c0 = half * 128 + g * 32;
        uint32_t d[32];
        TCGEN05_LD_32X32B_X32(d, tmem + woff + (uint32_t)c0);
        TCGEN05_WAIT_LD();
#pragma unroll
        for (int q = 0; q < 8; ++q) {
            float4 v;
            v.x = __uint_as_float(d[q * 4 + 0]) + sbias[c0 + q * 4 + 0];
            v.y = __uint_as_float(d[q * 4 + 1]) + sbias[c0 + q * 4 + 1];
            v.z = __uint_as_float(d[q * 4 + 2]) + sbias[c0 + q * 4 + 2];
            v.w = __uint_as_float(d[q * 4 + 3]) + sbias[c0 + q * 4 + 3];
            *(float4*)(orow + c0 + q * 4) = v;
        }
    }

    TCGEN05_FENCE_BEFORE();
    __syncthreads();
    if (wid == 0) {
        TCGEN05_DEALLOC(tmem, TMEM_COLS);
    }

#else  // ---------------- fallback: correct smem-tiled FFMA (plain sm_103) ----
    extern __shared__ float fsmem[];
    float* As = fsmem;                  // [128][33]
    float* Bs = fsmem + 128 * 33;       // [32][132]

    const int tid   = threadIdx.x;
    const int mtile = blockIdx.x;
    const int b     = blockIdx.y;
    const int ch    = fetch_index(indices, b);

    const float* __restrict__ xb = x + ((size_t)b * NROWS + mtile * 128) * INK;
    const float* __restrict__ wb = w + (size_t)ch * (INK * OUTN);

    const int r0 = (tid >> 4) * 8;      // 0..120
    const int c0 = (tid & 15) * 8;      // 0..120 (within 128-col group)

    for (int ng = 0; ng < 2; ++ng) {
        float acc[8][8];
#pragma unroll
        for (int i = 0; i < 8; ++i)
#pragma unroll
            for (int j = 0; j < 8; ++j) acc[i][j] = 0.0f;

        for (int kt = 0; kt < 8; ++kt) {
            __syncthreads();
            for (int i = tid; i < 128 * 32; i += 256) {
                int row = i >> 5, col = i & 31;
                As[row * 33 + col] = xb[(size_t)row * INK + kt * 32 + col];
            }
            for (int i = tid; i < 32 * 128; i += 256) {
                int row = i >> 7, col = i & 127;
                Bs[row * 132 + col] = wb[(size_t)(kt * 32 + row) * OUTN + ng * 128 + col];
            }
            __syncthreads();
#pragma unroll 8
            for (int kk = 0; kk < 32; ++kk) {
                float av[8], bv[8];
#pragma unroll
                for (int i = 0; i < 8; ++i) av[i] = As[(r0 + i) * 33 + kk];
#pragma unroll
                for (int j = 0; j < 8; ++j) bv[j] = Bs[kk * 132 + c0 + j];
#pragma unroll
                for (int i = 0; i < 8; ++i)
#pragma unroll
                    for (int j = 0; j < 8; ++j) acc[i][j] += av[i] * bv[j];
            }
        }

#pragma unroll
        for (int i = 0; i < 8; ++i) {
            float* orow = out + ((size_t)b * NROWS + mtile * 128 + r0 + i) * OUTN + ng * 128 + c0;
#pragma unroll
            for (int j = 0; j < 8; ++j)
                orow[j] = acc[i][j] + bias[(size_t)ch * OUTN + ng * 128 + c0 + j];
        }
        __syncthreads();
    }
#endif
}

extern "C" void kernel_launch(void* const* d_in, const int* in_sizes, int n_in,
                              void* d_out, int out_size) {
    const float* x       = (const float*)d_in[0];
    const void*  indices = d_in[1];
    const float* w       = (const float*)d_in[2];
    const float* bias    = (const float*)d_in[3];
    float* out = (float*)d_out;

    cudaFuncSetAttribute(alw_kernel,
                         cudaFuncAttributeMaxDynamicSharedMemorySize, SMEM_TOTAL);

    dim3 grid(NROWS / 128, BB);   // (8, 256)
    alw_kernel<<<grid, 256, SMEM_TOTAL>>>(x, indices, w, bias, out);
}

// round 8
// speedup vs baseline: 1.4540x; 1.1702x over previous
#include <cuda_runtime.h>
#include <cuda.h>
#include <cstdint>

#define BB    256
#define NROWS 1024
#define INK   256
#define OUTN  256

// SMEM layout (bytes) for tcgen05 path
#define SMEM_TMEM_PTR 0
#define SMEM_MDONE0   8
#define SMEM_MDONE1   16
#define SMEM_BFULL0   24
#define SMEM_BFULL1   32
#define SMEM_BIAS     64            // 256 floats
#define SMEM_A        2048          // 2 stages x 16KB (128 rows x 128B, SW128)
#define A_STAGE       16384
#define SMEM_B        34816         // 2 stages x 32KB (256 rows x 128B, SW128)
#define B_STAGE       32768
#define SMEM_TOTAL    100352

#define TMEM_COLS 256

// 64MB transposed-weight scratch: wT[b][n][k] = tf32(w[indices[b]][k][n])
// 1024B-aligned for TMA global-address requirements.
__device__ __align__(1024) float g_wT[(size_t)BB * OUTN * INK];

// Arch gate: tcgen05 only exists in the arch-specific (sm_103a) pass; the plain
// compute_103 pass gets a correct FFMA fallback.
#if defined(__CUDA_ARCH__) && (defined(__CUDA_ARCH_FEAT_SM103_ALL) || \
    (defined(__CUDA_ARCH_SPECIFIC__)))
#define ALW_TCGEN05 1
#else
#define ALW_TCGEN05 0
#endif

// int64-vs-int32 index buffer detection (values < 1024 -> int64 high words all 0)
static __device__ __forceinline__ int fetch_index(const void* p, int b) {
    const int* q = (const int*)p;
    int odd_or = q[1] | q[3] | q[5] | q[7] | q[9] | q[11] | q[13] | q[15];
    return (odd_or == 0) ? q[2 * b] : q[b];
}

static __device__ __forceinline__ float tf32r(float f) {
    uint32_t u;
    asm("cvt.rna.tf32.f32 %0, %1;" : "=r"(u) : "f"(f));
    return __uint_as_float(u);
}

// ---------------- Kernel 1: gather + transpose + tf32-round ----------------
__global__ void __launch_bounds__(256)
alw_transpose(const void* __restrict__ indices, const float* __restrict__ w) {
    __shared__ float t[32][33];
    const int b    = blockIdx.y;
    const int tile = blockIdx.x;          // 0..63
    const int k0   = (tile >> 3) * 32;
    const int n0   = (tile & 7) * 32;
    const int ch   = fetch_index(indices, b);
    const int tx = threadIdx.x, ty = threadIdx.y;

    const float* __restrict__ src = w + (size_t)ch * INK * OUTN;
#pragma unroll
    for (int r = 0; r < 32; r += 8)
        t[ty + r][tx] = src[(size_t)(k0 + ty + r) * OUTN + n0 + tx];
    __syncthreads();

    float* __restrict__ dst = g_wT + (size_t)b * OUTN * INK;
#pragma unroll
    for (int r = 0; r < 32; r += 8)
        dst[(size_t)(n0 + ty + r) * INK + k0 + tx] = tf32r(t[tx][ty + r]);
}

#if ALW_TCGEN05

// tcgen05 idesc, kind::tf32: c=F32(1)@[4:5], a=TF32(2)@[7:9], b=TF32(2)@[10:12],
// N>>3 @[17:22], M>>4 @[24:28]; K-major both
#define IDESC ((1u << 4) | (2u << 7) | (2u << 10) | ((OUTN / 8) << 17) | ((128 / 16) << 24))

#define SWZ(o) ((uint32_t)(o) ^ ((((uint32_t)(o)) >> 3) & 0x70))

// SW128 K-major smem descriptor base: layout=2, version=1, SBO=64, LBO=1
static __device__ __forceinline__ uint64_t make_desc(uint32_t addr) {
    const uint64_t base = (uint64_t(2) << 61) | (uint64_t(1) << 46) |
                          (uint64_t(64) << 32) | (uint64_t(1) << 16);
    return base | ((uint64_t)(addr >> 4) & 0x3FFF);
}

static __device__ __forceinline__ uint32_t smem_u32(const void* p) {
    uint32_t a;
    asm("{ .reg .u64 t; cvta.to.shared.u64 t, %1; cvt.u32.u64 %0, t; }" : "=r"(a) : "l"(p));
    return a;
}

#define MBARRIER_INIT(addr, cnt) \
    asm volatile("mbarrier.init.shared.b64 [%0], %1;" :: "r"((uint32_t)(addr)), "r"((uint32_t)(cnt)) : "memory")

#define MBARRIER_EXPECT_TX(addr, bytes) \
    asm volatile("mbarrier.arrive.expect_tx.shared.b64 _, [%0], %1;" \
                 :: "r"((uint32_t)(addr)), "r"((uint32_t)(bytes)) : "memory")

#define MBARRIER_WAIT_PARITY(mbar_addr, phase_parity) do {                                  \
    uint32_t _mbar = (uint32_t)(mbar_addr);                                                 \
    uint32_t _par  = (uint32_t)(phase_parity);                                              \
    uint32_t _done;                                                                         \
    asm volatile("{\n\t.reg .pred p;\n\t"                                                   \
                 "mbarrier.try_wait.parity.acquire.cta.shared::cta.b64 p, [%1], %2;\n\t"    \
                 "selp.b32 %0, 1, 0, p;\n\t}"                                               \
                 : "=r"(_done) : "r"(_mbar), "r"(_par) : "memory");                         \
    if (!_done) {                                                                           \
        asm volatile("{\n\t.reg .pred P1;\n\t"                                              \
            "WAIT_LOOP_%=:\n\t"                                                             \
            "mbarrier.try_wait.parity.acquire.cta.shared::cta.b64 P1, [%0], %1, 0x989680;\n\t" \
            "@P1 bra.uni WAIT_DONE_%=;\n\t"                                                 \
            "bra.uni WAIT_LOOP_%=;\n\t"                                                     \
            "WAIT_DONE_%=:\n\t}"                                                            \
            :: "r"(_mbar), "r"(_par) : "memory");                                           \
    }                                                                                       \
} while (0)

#define TMA_LOAD_3D(smem_addr, tmap_ptr, c0, c1, c2, mbar_addr) \
    asm volatile( \
        "cp.async.bulk.tensor.3d.shared::cta.global.tile.mbarrier::complete_tx::bytes " \
        "[%0], [%1, {%2, %3, %4}], [%5];" \
        :: "r"((uint32_t)(smem_addr)), "l"(tmap_ptr), \
           "r"((int32_t)(c0)), "r"((int32_t)(c1)), "r"((int32_t)(c2)), \
           "r"((uint32_t)(mbar_addr)) : "memory")

#define TCGEN05_ALLOC(smem_addr, ncols) \
    asm volatile("tcgen05.alloc.cta_group::1.sync.aligned.shared::cta.b32 [%0], %1;" \
                 :: "r"((uint32_t)(smem_addr)), "r"((uint32_t)(ncols)) : "memory")
#define TCGEN05_DEALLOC(tmem, ncols) \
    asm volatile("tcgen05.dealloc.cta_group::1.sync.aligned.b32 %0, %1;" \
                 :: "r"(tmem), "r"((uint32_t)(ncols)))
#define TCGEN05_RELINQ() \
    asm volatile("tcgen05.relinquish_alloc_permit.cta_group::1.sync.aligned;")
#define TCGEN05_COMMIT(mbar) \
    asm volatile("tcgen05.commit.cta_group::1.mbarrier::arrive::one.shared::cluster.b64 [%0];" \
                 :: "r"((uint32_t)(mbar)) : "memory")
#define TCGEN05_FENCE_AFTER() \
    asm volatile("tcgen05.fence::after_thread_sync;" ::: "memory")
#define TCGEN05_FENCE_BEFORE() \
    asm volatile("tcgen05.fence::before_thread_sync;" ::: "memory")
#define TCGEN05_WAIT_LD() \
    asm volatile("tcgen05.wait::ld.sync.aligned;" ::: "memory")

#define TCGEN05_LD_32X32B_X32(r, tmem_addr) \
    asm volatile( \
        "tcgen05.ld.sync.aligned.32x32b.x32.b32 " \
        "{%0, %1, %2, %3, %4, %5, %6, %7, " \
        " %8, %9, %10, %11, %12, %13, %14, %15, " \
        " %16, %17, %18, %19, %20, %21, %22, %23, " \
        " %24, %25, %26, %27, %28, %29, %30, %31}, [%32];" \
        : "=r"((r)[0]),  "=r"((r)[1]),  "=r"((r)[2]),  "=r"((r)[3]), \
          "=r"((r)[4]),  "=r"((r)[5]),  "=r"((r)[6]),  "=r"((r)[7]), \
          "=r"((r)[8]),  "=r"((r)[9]),  "=r"((r)[10]), "=r"((r)[11]), \
          "=r"((r)[12]), "=r"((r)[13]), "=r"((r)[14]), "=r"((r)[15]), \
          "=r"((r)[16]), "=r"((r)[17]), "=r"((r)[18]), "=r"((r)[19]), \
          "=r"((r)[20]), "=r"((r)[21]), "=r"((r)[22]), "=r"((r)[23]), \
          "=r"((r)[24]), "=r"((r)[25]), "=r"((r)[26]), "=r"((r)[27]), \
          "=r"((r)[28]), "=r"((r)[29]), "=r"((r)[30]), "=r"((r)[31]) \
        : "r"(tmem_addr))

static __device__ __forceinline__ void mma_tf32_ss(uint32_t d_tmem, uint64_t a_desc,
                                                   uint64_t b_desc, uint32_t idesc,
                                                   uint32_t enable) {
    asm volatile(
        "{\n\t"
        ".reg .pred p;\n\t"
        "setp.ne.u32 p, %4, 0;\n\t"
        "tcgen05.mma.cta_group::1.kind::tf32 [%0], %1, %2, %3, {%5, %5, %5, %5}, p;\n\t"
        "}"
        :: "r"(d_tmem), "l"(a_desc), "l"(b_desc), "r"(idesc), "r"(enable), "r"(0u)
        : "memory");
}

#endif // ALW_TCGEN05

// ---------------- Kernel 2: TMA-B + tcgen05 GEMM ----------------
__global__ void __launch_bounds__(256, 2)
alw_main(const __grid_constant__ CUtensorMap tmapB,
         const float* __restrict__ x,
         const void*  __restrict__ indices,
         const float* __restrict__ w,
         const float* __restrict__ bias,
         float* __restrict__ out) {
#if ALW_TCGEN05
    extern __shared__ char smem[];
    const uint32_t sb = smem_u32(smem);
    const int tid  = threadIdx.x;
    const int lane = tid & 31;
    const int wid  = tid >> 5;

    const int mtile = blockIdx.x;
    const int b     = blockIdx.y;
    const int ch    = fetch_index(indices, b);

    const float* __restrict__ xb = x + ((size_t)b * NROWS + mtile * 128) * INK;

    if (wid == 0) {
        TCGEN05_ALLOC(sb + SMEM_TMEM_PTR, TMEM_COLS);
        TCGEN05_RELINQ();
    }
    if (tid == 0) {
        MBARRIER_INIT(sb + SMEM_MDONE0, 1);
        MBARRIER_INIT(sb + SMEM_MDONE1, 1);
        MBARRIER_INIT(sb + SMEM_BFULL0, 1);
        MBARRIER_INIT(sb + SMEM_BFULL1, 1);
    }
    ((float*)(smem + SMEM_BIAS))[tid] = bias[(size_t)ch * OUTN + tid];
    __syncthreads();

    uint32_t tmem;
    asm volatile("ld.shared.b32 %0, [%1];" : "=r"(tmem) : "r"(sb + SMEM_TMEM_PTR));

    // A-load coordinates: 4 float4 per thread per 16KB chunk
    int a_row[4], a_c4[4];
#pragma unroll
    for (int i = 0; i < 4; ++i) {
        int idx = i * 256 + tid;
        a_row[i] = idx >> 3;
        a_c4[i]  = idx & 7;
    }

    // prefetch A chunk 0
    float4 pa[4];
#pragma unroll
    for (int i = 0; i < 4; ++i)
        pa[i] = *(const float4*)(xb + (size_t)a_row[i] * INK + a_c4[i] * 4);

#pragma unroll 1
    for (int kt = 0; kt < 8; ++kt) {
        const int buf = kt & 1;
        const uint32_t mdone = sb + (buf ? SMEM_MDONE1 : SMEM_MDONE0);
        const uint32_t bfull = sb + (buf ? SMEM_BFULL1 : SMEM_BFULL0);

        if (kt >= 2) {
            // this buffer's previous MMA (chunk kt-2) must be done before overwrite
            MBARRIER_WAIT_PARITY(mdone, ((kt - 2) >> 1) & 1);
        }

        // producer: kick TMA for B chunk (32 k-cols x 256 n-rows, SW128)
        if (tid == 0) {
            MBARRIER_EXPECT_TX(bfull, B_STAGE);
            TMA_LOAD_3D(sb + SMEM_B + buf * B_STAGE, &tmapB, kt * 32, 0, b, bfull);
        }

        // A: tf32-round + STS.128 into SW128 stage (conflict-free)
        {
            char* Ab = smem + SMEM_A + buf * A_STAGE;
#pragma unroll
            for (int i = 0; i < 4; ++i) {
                float4 t = make_float4(tf32r(pa[i].x), tf32r(pa[i].y),
                                       tf32r(pa[i].z), tf32r(pa[i].w));
                *(float4*)(Ab + SWZ(a_row[i] * 128 + a_c4[i] * 16)) = t;
            }
        }
        // prefetch next A chunk into registers
        if (kt < 7) {
            const int k0 = (kt + 1) * 32;
#pragma unroll
            for (int i = 0; i < 4; ++i)
                pa[i] = *(const float4*)(xb + (size_t)a_row[i] * INK + k0 + a_c4[i] * 4);
        }
        __syncthreads();

        if (tid == 0) {
            MBARRIER_WAIT_PARITY(bfull, (kt >> 1) & 1);
            asm volatile("fence.proxy.async.shared::cta;" ::: "memory");
            uint64_t ad = make_desc(sb + SMEM_A + buf * A_STAGE);
            uint64_t bd = make_desc(sb + SMEM_B + buf * B_STAGE);
#pragma unroll
            for (int kk = 0; kk < 4; ++kk) {
                mma_tf32_ss(tmem, ad + kk * 2, bd + kk * 2, IDESC,
                            (uint32_t)((kt | kk) != 0));
            }
            TCGEN05_COMMIT(mdone);
        }
    }

    // Final sync: each thread's last in-loop wait on mdoneX consumed completion
    // #3 (parity 0); by per-thread program order, a parity-1 wait here can only
    // be satisfied by completion #4 (the last MMA commit). Exactly one wait —
    // parities 0,1,0,1 toggle and a 5th completion never arrives.
    MBARRIER_WAIT_PARITY(sb + SMEM_MDONE0, 1);
    MBARRIER_WAIT_PARITY(sb + SMEM_MDONE1, 1);
    TCGEN05_FENCE_AFTER();

    const int sub  = wid & 3;
    const int half = wid >> 2;
    const uint32_t woff = (uint32_t)sub << 21;
    const int m = mtile * 128 + sub * 32 + lane;
    float* __restrict__ orow = out + ((size_t)b * NROWS + m) * OUTN;
    const float* sbias = (const float*)(smem + SMEM_BIAS);

#pragma unroll
    for (int g = 0; g < 4; ++g) {
        const int c0 = half * 128 + g * 32;
        uint32_t d[32];
        TCGEN05_LD_32X32B_X32(d, tmem + woff + (uint32_t)c0);
        TCGEN05_WAIT_LD();
#pragma unroll
        for (int q = 0; q < 8; ++q) {
            float4 v;
            v.x = __uint_as_float(d[q * 4 + 0]) + sbias[c0 + q * 4 + 0];
            v.y = __uint_as_float(d[q * 4 + 1]) + sbias[c0 + q * 4 + 1];
            v.z = __uint_as_float(d[q * 4 + 2]) + sbias[c0 + q * 4 + 2];
            v.w = __uint_as_float(d[q * 4 + 3]) + sbias[c0 + q * 4 + 3];
            *(float4*)(orow + c0 + q * 4) = v;
        }
    }

    TCGEN05_FENCE_BEFORE();
    __syncthreads();
    if (wid == 0) {
        TCGEN05_DEALLOC(tmem, TMEM_COLS);
    }

#else  // ---------------- fallback: correct smem-tiled FFMA (plain sm_103) ----
    extern __shared__ float fsmem[];
    float* As = fsmem;                  // [128][33]
    float* Bs = fsmem + 128 * 33;       // [32][132]

    const int tid   = threadIdx.x;
    const int mtile = blockIdx.x;
    const int b     = blockIdx.y;
    const int ch    = fetch_index(indices, b);

    const float* __restrict__ xb = x + ((size_t)b * NROWS + mtile * 128) * INK;
    const float* __restrict__ wb = w + (size_t)ch * (INK * OUTN);

    const int r0 = (tid >> 4) * 8;
    const int c0 = (tid & 15) * 8;

    for (int ng = 0; ng < 2; ++ng) {
        float acc[8][8];
#pragma unroll
        for (int i = 0; i < 8; ++i)
#pragma unroll
            for (int j = 0; j < 8; ++j) acc[i][j] = 0.0f;

        for (int kt = 0; kt < 8; ++kt) {
            __syncthreads();
            for (int i = tid; i < 128 * 32; i += 256) {
                int row = i >> 5, col = i & 31;
                As[row * 33 + col] = xb[(size_t)row * INK + kt * 32 + col];
            }
            for (int i = tid; i < 32 * 128; i += 256) {
                int row = i >> 7, col = i & 127;
                Bs[row * 132 + col] = wb[(size_t)(kt * 32 + row) * OUTN + ng * 128 + col];
            }
            __syncthreads();
#pragma unroll 8
            for (int kk = 0; kk < 32; ++kk) {
                float av[8], bv[8];
#pragma unroll
                for (int i = 0; i < 8; ++i) av[i] = As[(r0 + i) * 33 + kk];
#pragma unroll
                for (int j = 0; j < 8; ++j) bv[j] = Bs[kk * 132 + c0 + j];
#pragma unroll
                for (int i = 0; i < 8; ++i)
#pragma unroll
                    for (int j = 0; j < 8; ++j) acc[i][j] += av[i] * bv[j];
            }
        }

#pragma unroll
        for (int i = 0; i < 8; ++i) {
            float* orow = out + ((size_t)b * NROWS + mtile * 128 + r0 + i) * OUTN + ng * 128 + c0;
#pragma unroll
            for (int j = 0; j < 8; ++j)
                orow[j] = acc[i][j] + bias[(size_t)ch * OUTN + ng * 128 + c0 + j];
        }
        __syncthreads();
    }
#endif
}

// ---------------- host ----------------
typedef CUresult (*PFN_encodeTiled)(
    CUtensorMap*, CUtensorMapDataType, cuuint32_t, void*,
    const cuuint64_t*, const cuuint64_t*, const cuuint32_t*, const cuuint32_t*,
    CUtensorMapInterleave, CUtensorMapSwizzle, CUtensorMapL2promotion,
    CUtensorMapFloatOOBfill);

extern "C" void kernel_launch(void* const* d_in, const int* in_sizes, int n_in,
                              void* d_out, int out_size) {
    const float* x       = (const float*)d_in[0];
    const void*  indices = d_in[1];
    const float* w       = (const float*)d_in[2];
    const float* bias    = (const float*)d_in[3];
    float* out = (float*)d_out;

    // resolve cuTensorMapEncodeTiled via cudart (no -lcuda needed)
    static PFN_encodeTiled enc = nullptr;
    if (!enc) {
        void* p = nullptr;
        cudaDriverEntryPointQueryResult qr;
        cudaGetDriverEntryPoint("cuTensorMapEncodeTiled", &p, cudaEnableDefault, &qr);
        enc = (PFN_encodeTiled)p;
    }

    void* wT_ptr = nullptr;
    cudaGetSymbolAddress(&wT_ptr, g_wT);

    // B tensormap over g_wT viewed as [b=256][n=256][k=256] f32, box (32k, 256n, 1b), SW128
    CUtensorMap tmapB;
    cuuint64_t dims[3]    = {INK, OUTN, BB};
    cuuint64_t strides[2] = {(cuuint64_t)INK * 4, (cuuint64_t)INK * OUTN * 4};
    cuuint32_t box[3]     = {32, 256, 1};
    cuuint32_t estr[3]    = {1, 1, 1};
    enc(&tmapB, CU_TENSOR_MAP_DATA_TYPE_FLOAT32, 3, wT_ptr, dims, strides, box, estr,
        CU_TENSOR_MAP_INTERLEAVE_NONE, CU_TENSOR_MAP_SWIZZLE_128B,
        CU_TENSOR_MAP_L2_PROMOTION_L2_128B, CU_TENSOR_MAP_FLOAT_OOB_FILL_NONE);

    // pass 1: gather + transpose + tf32-round weights
    alw_transpose<<<dim3(64, BB), dim3(32, 8)>>>(indices, w);

    // pass 2: GEMM
    cudaFuncSetAttribute(alw_main,
                         cudaFuncAttributeMaxDynamicSharedMemorySize, SMEM_TOTAL);
    alw_main<<<dim3(NROWS / 128, BB), 256, SMEM_TOTAL>>>(tmapB, x, indices, w, bias, out);
}